// round 10
// baseline (speedup 1.0000x reference)
#include <cuda_runtime.h>

#define NB 4096
#define NF 1024
#define NR 64
#define NK 32
#define ND 16
#define TB 16
#define THREADS 256
#define RSPLIT 2
#define RPB (NR / RSPLIT)
#define LOG_2PI 1.8378770664093453f

typedef unsigned long long ull;

// Duplicated packed coefficients per (r,d,k): {inv,inv} and {nmi,nmi}
// (inv = 1/scale, nmi = -mean/scale). 16 B per entry, lanes k contiguous
// -> one LDG.128 per (d, lane), 512 B/warp contiguous.
__device__ ulonglong2 g_coefd[NR * ND * NK];   // 512 KB, L2-resident
// g_c[r*K+k] = -(sum_d log scale) - 0.5*D*log(2pi)
__device__ float g_c[NR * NK];

__device__ __forceinline__ ull dup2(float v) {
    ull r; asm("mov.b64 %0, {%1, %1};" : "=l"(r) : "f"(v)); return r;
}
__device__ __forceinline__ ull fma2(ull a, ull b, ull c) {
    ull d; asm("fma.rn.f32x2 %0, %1, %2, %3;" : "=l"(d) : "l"(a), "l"(b), "l"(c));
    return d;
}
__device__ __forceinline__ void unpk2(ull v, float& lo, float& hi) {
    asm("mov.b64 {%0, %1}, %2;" : "=f"(lo), "=f"(hi) : "l"(v));
}

__global__ void prep_kernel(const float* __restrict__ means,
                            const float* __restrict__ scales) {
    int id = blockIdx.x * blockDim.x + threadIdx.x;  // r*NK + k
    if (id >= NR * NK) return;
    int r = id / NK, k = id % NK;
    const float* m = means + (size_t)id * ND;
    const float* s = scales + (size_t)id * ND;
    float logdet = 0.f;
#pragma unroll
    for (int d = 0; d < ND; d++) {
        float sv = s[d];
        float iv = 1.0f / sv;
        ulonglong2 e;
        e.x = dup2(iv);
        e.y = dup2(-m[d] * iv);
        g_coefd[((size_t)r * ND + d) * NK + k] = e;
        logdet += logf(sv);
    }
    g_c[id] = -logdet - 0.5f * ND * LOG_2PI;
}

// Quad tile: slot (c, p) holds rows {4p..4p+3} of column c as float4 at
// byte offset c*64 + p*16. Hot-loop reads are lane-uniform LDS.128
// broadcasts (N=1), so no padding is needed; the fill is quad-major
// (slot i -> addr i*16) so STS.128 is sequential and conflict-free.
#define XT_BYTES (NF * 64)   // 65536

__global__ void __launch_bounds__(THREADS, 3) gauss_kernel(
        const float* __restrict__ x,
        const int* __restrict__ regions32,   // raw bits; dtype sniffed below
        float* __restrict__ out) {
    extern __shared__ char smem[];
    char* xt = smem;                               // quad tile, 64 KB
    int* reg_s = (int*)(smem + XT_BYTES);          // [RPB*ND] pre-scaled offs
    __shared__ int s_nonzero_odd;
    int tid = threadIdx.x;
    int b0 = blockIdx.x * TB;
    int r0 = blockIdx.y * RPB;

    if (tid == 0) s_nonzero_odd = 0;
    __syncthreads();

    // Dtype sniff: regions may be int64 (little-endian, values < 1024) or
    // int32. If int64, every odd 32-bit word of the first 512 words is zero.
    {
        int nz = 0;
        for (int i = tid; i < 256; i += THREADS)
            nz |= regions32[2 * i + 1];
        if (nz) atomicOr(&s_nonzero_odd, 1);
    }
    __syncthreads();
    int is32 = s_nonzero_odd;                // 1 -> int32, 0 -> int64

    // Fill quad tile: slot i = c*4 + p -> addr i*16 (sequential STS.128).
    for (int i = tid; i < NF * 4; i += THREADS) {
        int c = i >> 2, p = i & 3;
        const float* xp = x + (size_t)(b0 + 4 * p) * NF + c;
        float4 v;
        v.x = xp[0 * NF];
        v.y = xp[1 * NF];
        v.z = xp[2 * NF];
        v.w = xp[3 * NF];
        *(float4*)(xt + (size_t)i * 16) = v;
    }
    // Region index slice -> pre-scaled byte offsets c*64.
    for (int i = tid; i < RPB * ND; i += THREADS) {
        int g = r0 * ND + i;
        int v = is32 ? regions32[g] : regions32[2 * g];
        reg_s[i] = (v & (NF - 1)) << 6;
    }
    __syncthreads();

    int w = tid >> 5, l = tid & 31;          // lane l == k
    // Each warp: all 16 rows (4 quads) for 4 regions.
    for (int it = 0; it < RPB / 8; it++) {
        int rloc = w * (RPB / 8) + it;
        int rr = r0 + rloc;
        const ulonglong2* cgd = g_coefd + (size_t)rr * ND * NK + l;
        float C = g_c[rr * NK + l];
        const int* rp = reg_s + rloc * ND;

        ull accA[4], accB[4];
#pragma unroll
        for (int p = 0; p < 4; p++) { accA[p] = 0; accB[p] = 0; }

        // Software-pipelined coef loads: 4-d chunks, double-buffered.
        ulonglong2 cb[4], cn[4];
#pragma unroll
        for (int j = 0; j < 4; j++) cb[j] = cgd[j * NK];

#pragma unroll
        for (int ch = 0; ch < 4; ch++) {
            if (ch < 3) {
#pragma unroll
                for (int j = 0; j < 4; j++)
                    cn[j] = cgd[(4 * (ch + 1) + j) * NK];
            }
#pragma unroll
            for (int j = 0; j < 4; j++) {
                int Pd = rp[4 * ch + j];         // broadcast LDS
                const char* a = xt + Pd;
                ull ii = cb[j].x, nn = cb[j].y;
#pragma unroll
                for (int p = 0; p < 4; p++) {
                    ulonglong2 X = *(const ulonglong2*)(a + p * 16);
                    ull z0 = fma2(X.x, ii, nn);
                    accA[p] = fma2(z0, z0, accA[p]);
                    ull z1 = fma2(X.y, ii, nn);
                    accB[p] = fma2(z1, z1, accB[p]);
                }
            }
#pragma unroll
            for (int j = 0; j < 4; j++) cb[j] = cn[j];
        }

        // out[b][r][k]: lanes contiguous in k -> coalesced 128B stores.
        const size_t bs = (size_t)NR * NK;
#pragma unroll
        for (int p = 0; p < 4; p++) {
            float s0, s1, s2, s3;
            unpk2(accA[p], s0, s1);
            unpk2(accB[p], s2, s3);
            size_t ob = ((size_t)(b0 + 4 * p) * NR + rr) * NK + l;
            out[ob]          = fmaf(s0, -0.5f, C);
            out[ob + bs]     = fmaf(s1, -0.5f, C);
            out[ob + 2 * bs] = fmaf(s2, -0.5f, C);
            out[ob + 3 * bs] = fmaf(s3, -0.5f, C);
        }
    }
}

extern "C" void kernel_launch(void* const* d_in, const int* in_sizes, int n_in,
                              void* d_out, int out_size) {
    const float* x       = (const float*)d_in[0];
    const int* regions   = (const int*)d_in[1];   // int32 or int64 bits, sniffed
    const float* means   = (const float*)d_in[2];
    const float* scales  = (const float*)d_in[3];
    float* out = (float*)d_out;

    prep_kernel<<<(NR * NK + 255) / 256, 256>>>(means, scales);

    size_t smem = XT_BYTES + RPB * ND * sizeof(int);   // 67584 B
    cudaFuncSetAttribute(gauss_kernel,
                         cudaFuncAttributeMaxDynamicSharedMemorySize, (int)smem);
    dim3 grid(NB / TB, RSPLIT);
    gauss_kernel<<<grid, THREADS, smem>>>(x, regions, out);
}

// round 14
// speedup vs baseline: 2.5030x; 2.5030x over previous
#include <cuda_runtime.h>

#define NB 4096
#define NF 1024
#define NR 64
#define NK 32
#define ND 16
#define TB 16
#define THREADS 256
#define RSPLIT 2
#define RPB (NR / RSPLIT)
#define LOG_2PI 1.8378770664093453f

typedef unsigned long long ull;

// Precomputed per-(r,k,d) coefficients:
//   inv = 1/scale, nmi = -mean/scale  packed as float4 {inv0,nmi0,inv1,nmi1}
//   layout [r][d/2][k] so lane k loads a float4 per 2 d's (coalesced LDG.128).
__device__ float4 g_coef4[NR * (ND / 2) * NK];
// g_c[r*K+k] = -(sum_d log scale) - 0.5*D*log(2pi)
__device__ float g_c[NR * NK];

__global__ void prep_kernel(const float* __restrict__ means,
                            const float* __restrict__ scales) {
    int id = blockIdx.x * blockDim.x + threadIdx.x;  // r*NK + k
    if (id >= NR * NK) return;
    int r = id / NK, k = id % NK;
    const float* m = means + (size_t)id * ND;
    const float* s = scales + (size_t)id * ND;
    float logdet = 0.f;
#pragma unroll
    for (int d2 = 0; d2 < ND / 2; d2++) {
        float s0 = s[2 * d2], s1 = s[2 * d2 + 1];
        float i0 = 1.0f / s0, i1 = 1.0f / s1;
        float4 c;
        c.x = i0; c.y = -m[2 * d2] * i0;
        c.z = i1; c.w = -m[2 * d2 + 1] * i1;
        g_coef4[(r * (ND / 2) + d2) * NK + k] = c;
        logdet += logf(s0) + logf(s1);
    }
    g_c[id] = -logdet - 0.5f * ND * LOG_2PI;
}

// -------- packed f32x2 helpers (FFMA2 path: PTX-only on sm_103a) --------
__device__ __forceinline__ ull pk2(float v) {          // {v, v}
    ull r; asm("mov.b64 %0, {%1, %1};" : "=l"(r) : "f"(v)); return r;
}
__device__ __forceinline__ ull fma2(ull a, ull b, ull c) {
    ull d; asm("fma.rn.f32x2 %0, %1, %2, %3;" : "=l"(d) : "l"(a), "l"(b), "l"(c));
    return d;
}
__device__ __forceinline__ void unpk2(ull v, float& lo, float& hi) {
    asm("mov.b64 {%0, %1}, %2;" : "=f"(lo), "=f"(hi) : "l"(v));
}

// Quad tile: slot (c, p) holds rows {4p..4p+3} of column c as float4 at
// byte offset c*64 + p*16. Hot-loop reads are lane-uniform LDS.128
// broadcasts (N=1) -> no padding needed; fill is slot-sequential STS.128.
#define XT_BYTES (NF * 64)   // 65536

__global__ void __launch_bounds__(THREADS, 3) gauss_kernel(
        const float* __restrict__ x,
        const int* __restrict__ regions32,   // raw bits; dtype sniffed below
        float* __restrict__ out) {
    extern __shared__ char smem[];
    char* xt = smem;                               // quad tile, 64 KB
    int* reg_s = (int*)(smem + XT_BYTES);          // [RPB*ND] pre-scaled offs
    __shared__ int s_nonzero_odd;
    int tid = threadIdx.x;
    int b0 = blockIdx.x * TB;
    int r0 = blockIdx.y * RPB;

    if (tid == 0) s_nonzero_odd = 0;
    __syncthreads();

    // Dtype sniff: regions may be int64 (little-endian, values < 1024) or
    // int32. If int64, every odd 32-bit word of the first 512 words is zero.
    {
        int nz = 0;
        for (int i = tid; i < 256; i += THREADS)
            nz |= regions32[2 * i + 1];
        if (nz) atomicOr(&s_nonzero_odd, 1);
    }
    __syncthreads();
    int is32 = s_nonzero_odd;                // 1 -> int32, 0 -> int64

    // Fill quad tile: slot i = c*4 + p -> addr i*16 (sequential STS.128).
    for (int i = tid; i < NF * 4; i += THREADS) {
        int c = i >> 2, p = i & 3;
        const float* xp = x + (size_t)(b0 + 4 * p) * NF + c;
        float4 v;
        v.x = xp[0 * NF];
        v.y = xp[1 * NF];
        v.z = xp[2 * NF];
        v.w = xp[3 * NF];
        *(float4*)(xt + (size_t)i * 16) = v;
    }
    // Region index slice -> pre-scaled byte offsets c*64.
    for (int i = tid; i < RPB * ND; i += THREADS) {
        int g = r0 * ND + i;
        int v = is32 ? regions32[g] : regions32[2 * g];
        reg_s[i] = (v & (NF - 1)) << 6;
    }
    __syncthreads();

    int w = tid >> 5, l = tid & 31;          // lane l == k
    // Each warp processes ALL 16 rows (4 quads) of the tile for 4 regions.
    for (int it = 0; it < RPB / 8; it++) {
        int rloc = w * (RPB / 8) + it;
        int rr = r0 + rloc;
        const float4* cg = g_coef4 + rr * (ND / 2) * NK + l;
        float C = g_c[rr * NK + l];
        const int4* rp4 = (const int4*)(reg_s + rloc * ND);

        ull acc[8];                          // acc[j]: rows {2j, 2j+1}
#pragma unroll
        for (int j = 0; j < 8; j++) acc[j] = 0;

#pragma unroll
        for (int q = 0; q < 4; q++) {        // q covers d = 4q .. 4q+3
            int4 P = rp4[q];
            float4 c0 = cg[(2 * q) * NK];    // coefs for d = 4q, 4q+1
            float4 c1 = cg[(2 * q + 1) * NK];// coefs for d = 4q+2, 4q+3
            ull i0 = pk2(c0.x), n0 = pk2(c0.y);
            ull i1 = pk2(c0.z), n1 = pk2(c0.w);
            ull i2 = pk2(c1.x), n2 = pk2(c1.y);
            ull i3 = pk2(c1.z), n3 = pk2(c1.w);
            const char* a0 = xt + P.x;       // lane-uniform bases; p*16 is an
            const char* a1 = xt + P.y;       // immediate in the LDS.128 below
            const char* a2 = xt + P.z;
            const char* a3 = xt + P.w;
#pragma unroll
            for (int p = 0; p < 4; p++) {    // quad p = rows 4p..4p+3
                ull z;
                ulonglong2 X0 = *(const ulonglong2*)(a0 + p * 16);
                z = fma2(X0.x, i0, n0); acc[2 * p]     = fma2(z, z, acc[2 * p]);
                z = fma2(X0.y, i0, n0); acc[2 * p + 1] = fma2(z, z, acc[2 * p + 1]);
                ulonglong2 X1 = *(const ulonglong2*)(a1 + p * 16);
                z = fma2(X1.x, i1, n1); acc[2 * p]     = fma2(z, z, acc[2 * p]);
                z = fma2(X1.y, i1, n1); acc[2 * p + 1] = fma2(z, z, acc[2 * p + 1]);
                ulonglong2 X2 = *(const ulonglong2*)(a2 + p * 16);
                z = fma2(X2.x, i2, n2); acc[2 * p]     = fma2(z, z, acc[2 * p]);
                z = fma2(X2.y, i2, n2); acc[2 * p + 1] = fma2(z, z, acc[2 * p + 1]);
                ulonglong2 X3 = *(const ulonglong2*)(a3 + p * 16);
                z = fma2(X3.x, i3, n3); acc[2 * p]     = fma2(z, z, acc[2 * p]);
                z = fma2(X3.y, i3, n3); acc[2 * p + 1] = fma2(z, z, acc[2 * p + 1]);
            }
        }
        // out[b][r][k]: lanes contiguous in k -> coalesced 128B stores.
#pragma unroll
        for (int j = 0; j < 8; j++) {
            float s0, s1;
            unpk2(acc[j], s0, s1);
            size_t ob = ((size_t)(b0 + 2 * j) * NR + rr) * NK + l;
            out[ob] = fmaf(s0, -0.5f, C);
            out[ob + (size_t)NR * NK] = fmaf(s1, -0.5f, C);
        }
    }
}

extern "C" void kernel_launch(void* const* d_in, const int* in_sizes, int n_in,
                              void* d_out, int out_size) {
    const float* x       = (const float*)d_in[0];
    const int* regions   = (const int*)d_in[1];   // int32 or int64 bits, sniffed
    const float* means   = (const float*)d_in[2];
    const float* scales  = (const float*)d_in[3];
    float* out = (float*)d_out;

    prep_kernel<<<(NR * NK + 255) / 256, 256>>>(means, scales);

    size_t smem = XT_BYTES + RPB * ND * sizeof(int);   // 67584 B
    cudaFuncSetAttribute(gauss_kernel,
                         cudaFuncAttributeMaxDynamicSharedMemorySize, (int)smem);
    dim3 grid(NB / TB, RSPLIT);
    gauss_kernel<<<grid, THREADS, smem>>>(x, regions, out);
}

// round 15
// speedup vs baseline: 2.6490x; 1.0583x over previous
#include <cuda_runtime.h>

#define NB 4096
#define NF 1024
#define NR 64
#define NK 32
#define ND 16
#define TB 16
#define THREADS 512
#define RSPLIT 2
#define RPB (NR / RSPLIT)
#define LOG_2PI 1.8378770664093453f

typedef unsigned long long ull;

// Precomputed per-(r,k,d) coefficients:
//   inv = 1/scale, nmi = -mean/scale  packed as float4 {inv0,nmi0,inv1,nmi1}
//   layout [r][d/2][k] so lane k loads a float4 per 2 d's (coalesced LDG.128).
__device__ float4 g_coef4[NR * (ND / 2) * NK];
// g_c[r*K+k] = -(sum_d log scale) - 0.5*D*log(2pi)
__device__ float g_c[NR * NK];

__global__ void prep_kernel(const float* __restrict__ means,
                            const float* __restrict__ scales) {
    int id = blockIdx.x * blockDim.x + threadIdx.x;  // r*NK + k
    if (id >= NR * NK) return;
    int r = id / NK, k = id % NK;
    const float* m = means + (size_t)id * ND;
    const float* s = scales + (size_t)id * ND;
    float logdet = 0.f;
#pragma unroll
    for (int d2 = 0; d2 < ND / 2; d2++) {
        float s0 = s[2 * d2], s1 = s[2 * d2 + 1];
        float i0 = 1.0f / s0, i1 = 1.0f / s1;
        float4 c;
        c.x = i0; c.y = -m[2 * d2] * i0;
        c.z = i1; c.w = -m[2 * d2 + 1] * i1;
        g_coef4[(r * (ND / 2) + d2) * NK + k] = c;
        logdet += logf(s0) + logf(s1);
    }
    g_c[id] = -logdet - 0.5f * ND * LOG_2PI;
}

// -------- packed f32x2 helpers (FFMA2 path: PTX-only on sm_103a) --------
__device__ __forceinline__ ull pk2(float v) {          // {v, v}
    ull r; asm("mov.b64 %0, {%1, %1};" : "=l"(r) : "f"(v)); return r;
}
__device__ __forceinline__ ull fma2(ull a, ull b, ull c) {
    ull d; asm("fma.rn.f32x2 %0, %1, %2, %3;" : "=l"(d) : "l"(a), "l"(b), "l"(c));
    return d;
}
__device__ __forceinline__ void unpk2(ull v, float& lo, float& hi) {
    asm("mov.b64 {%0, %1}, %2;" : "=f"(lo), "=f"(hi) : "l"(v));
}

// Transposed pair-tile byte offset for column c, row-pair p:
//   64 B per column (8 pairs) + (c>>2)*8 pad so fill-phase STS.64 spreads
//   over all 16 bank-pairs; hot-loop reads are lane-uniform broadcasts (N=1).
#define XT_BYTES (NF * 64 + (NF / 4) * 8)   // 67584

__global__ void __launch_bounds__(THREADS, 2) gauss_kernel(
        const float* __restrict__ x,
        const int* __restrict__ regions32,   // raw bits; dtype sniffed below
        float* __restrict__ out) {
    extern __shared__ char smem[];
    char* xt = smem;                               // transposed pair tile
    int* reg_s = (int*)(smem + XT_BYTES);          // [RPB*ND] pre-scaled offs
    __shared__ int s_nonzero_odd;
    int tid = threadIdx.x;
    int b0 = blockIdx.x * TB;
    int r0 = blockIdx.y * RPB;

    if (tid == 0) s_nonzero_odd = 0;
    __syncthreads();

    // Dtype sniff: regions may be int64 (little-endian, values < 1024) or
    // int32. If int64, every odd 32-bit word of the first 512 words is zero.
    {
        int nz = 0;
        for (int i = tid; i < 256; i += THREADS)
            nz |= regions32[2 * i + 1];
        if (nz) atomicOr(&s_nonzero_odd, 1);
    }
    __syncthreads();
    int is32 = s_nonzero_odd;                // 1 -> int32, 0 -> int64

    // Fill transposed pair tile: lanes take consecutive c (coalesced LDG),
    // each thread packs rows {2p, 2p+1} of column c into one float2.
    for (int i = tid; i < NF * (TB / 2); i += THREADS) {
        int c = i & (NF - 1);
        int p = i >> 10;                     // 0..7
        float lo = x[(size_t)(b0 + 2 * p) * NF + c];
        float hi = x[(size_t)(b0 + 2 * p + 1) * NF + c];
        int off = c * 64 + ((c >> 2) << 3) + (p << 3);
        *(float2*)(xt + off) = make_float2(lo, hi);
    }
    // Region index slice -> pre-scaled byte offsets P(c).
    for (int i = tid; i < RPB * ND; i += THREADS) {
        int g = r0 * ND + i;
        int v = is32 ? regions32[g] : regions32[2 * g];
        int c = v & (NF - 1);
        reg_s[i] = c * 64 + ((c >> 2) << 3);
    }
    __syncthreads();

    int w = tid >> 5, l = tid & 31;          // lane l == k
    // Each of the 16 warps processes ALL 8 row-pairs for 2 regions.
    for (int it = 0; it < RPB / 16; it++) {
        int rloc = w * (RPB / 16) + it;
        int rr = r0 + rloc;
        const float4* cg = g_coef4 + rr * (ND / 2) * NK + l;
        float C = g_c[rr * NK + l];
        const int4* rp4 = (const int4*)(reg_s + rloc * ND);

        ull acc[8];
#pragma unroll
        for (int p = 0; p < 8; p++) acc[p] = 0;

#pragma unroll
        for (int q = 0; q < 4; q++) {        // q covers d = 4q .. 4q+3
            int4 P = rp4[q];
            float4 c0 = cg[(2 * q) * NK];    // coefs for d = 4q, 4q+1
            float4 c1 = cg[(2 * q + 1) * NK];// coefs for d = 4q+2, 4q+3
            ull i0 = pk2(c0.x), n0 = pk2(c0.y);
            ull i1 = pk2(c0.z), n1 = pk2(c0.w);
            ull i2 = pk2(c1.x), n2 = pk2(c1.y);
            ull i3 = pk2(c1.z), n3 = pk2(c1.w);
            const char* a0 = xt + P.x;       // lane-uniform bases; p*8 is an
            const char* a1 = xt + P.y;       // immediate in the LDS below
            const char* a2 = xt + P.z;
            const char* a3 = xt + P.w;
#pragma unroll
            for (int p = 0; p < 8; p++) {
                ull z;
                z = fma2(*(const ull*)(a0 + p * 8), i0, n0); acc[p] = fma2(z, z, acc[p]);
                z = fma2(*(const ull*)(a1 + p * 8), i1, n1); acc[p] = fma2(z, z, acc[p]);
                z = fma2(*(const ull*)(a2 + p * 8), i2, n2); acc[p] = fma2(z, z, acc[p]);
                z = fma2(*(const ull*)(a3 + p * 8), i3, n3); acc[p] = fma2(z, z, acc[p]);
            }
        }
        // out[b][r][k]: lanes contiguous in k -> coalesced 128B stores.
#pragma unroll
        for (int p = 0; p < 8; p++) {
            float s0, s1;
            unpk2(acc[p], s0, s1);
            size_t ob = ((size_t)(b0 + 2 * p) * NR + rr) * NK + l;
            out[ob] = fmaf(s0, -0.5f, C);
            out[ob + (size_t)NR * NK] = fmaf(s1, -0.5f, C);
        }
    }
}

extern "C" void kernel_launch(void* const* d_in, const int* in_sizes, int n_in,
                              void* d_out, int out_size) {
    const float* x       = (const float*)d_in[0];
    const int* regions   = (const int*)d_in[1];   // int32 or int64 bits, sniffed
    const float* means   = (const float*)d_in[2];
    const float* scales  = (const float*)d_in[3];
    float* out = (float*)d_out;

    prep_kernel<<<(NR * NK + 255) / 256, 256>>>(means, scales);

    size_t smem = XT_BYTES + RPB * ND * sizeof(int);   // 69632 B
    cudaFuncSetAttribute(gauss_kernel,
                         cudaFuncAttributeMaxDynamicSharedMemorySize, (int)smem);
    dim3 grid(NB / TB, RSPLIT);
    gauss_kernel<<<grid, THREADS, smem>>>(x, regions, out);
}